// round 17
// baseline (speedup 1.0000x reference)
#include <cuda_runtime.h>
#include <cuda_fp16.h>
#include <math_constants.h>

#define N_ENT   100000
#define N_USR   50000
#define N_EDGE  1000000
#define C       64
#define N_FACT  4
#define N_RELM1 9
#define TEMPR   0.2f
// 1 / (2*sqrt(32))
#define INV_SCALE 0.08838834764831845f

#define SCAN_B  1024
#define NB_E    ((N_ENT + SCAN_B - 1) / SCAN_B)   // 98
#define NB_U    ((N_USR + SCAN_B - 1) / SCAN_B)   // 49
#define SBK     ((N_ENT + SCAN_B - 1) / SCAN_B)   // 98 score blocks

#define KGB     (N_ENT * 32 / 256)                // 12500 blocks (warp per entity)
#define UIB     (N_USR * 32 / 256)                // 6250 blocks (warp per user)
#define EB      ((N_EDGE + 255) / 256)            // 3907 edge blocks
#define HB      (N_ENT * C / 4 / 256)             // 6250 fp16-staging blocks

typedef unsigned long long u64;

// ---------------- scratch (device globals; no allocation) ----------------
__device__ __align__(16) float g_V[N_RELM1 * C];     // W W^T w^T, pre-scaled
__device__ float g_wn2[N_RELM1];
__device__ __align__(16) float g_dw[N_FACT * C];     // softmax(att) @ weight
__device__ __align__(16) float g_Sme[N_ENT * 12];    // exp(E·V_r), padded to 12
__device__ __align__(16) __half g_entH[N_ENT * C];   // fp16 copy of entity_emb
__device__ __align__(16) __half g_entAH[N_ENT * C];  // fp16 ent after hop0 norm
__device__ __align__(16) float g_usrA[N_USR * C];    // usr after hop0 norm (fp32)
__device__ float g_mask[N_EDGE];                     // unnormalized e2 per CSR pos
__device__ u64 g_histE[N_ENT];                       // packed per-head type histogram
__device__ int g_cntE[N_ENT], g_curE[N_ENT];
__device__ int g_cntU[N_USR], g_curU[N_USR];
__device__ int g_offE[N_ENT + 1];
__device__ int g_offU[N_USR + 1];
__device__ int  g_pkE[N_EDGE];                       // CSR-ordered (tail | type<<20)
__device__ __align__(8) int2 g_uiP[N_EDGE];          // CSR-ordered (col, val bits)
__device__ int g_bsumE[128], g_brdyE[128];
__device__ int g_bsumU[128], g_brdyU[128];

// ---------------- packed f32x2 helpers (sm_103a FFMA2 path) ----------------
__device__ __forceinline__ u64 f2mul(u64 x, u64 y) {
    u64 d; asm("mul.rn.f32x2 %0,%1,%2;" : "=l"(d) : "l"(x), "l"(y)); return d;
}
__device__ __forceinline__ u64 f2add(u64 x, u64 y) {
    u64 d; asm("add.rn.f32x2 %0,%1,%2;" : "=l"(d) : "l"(x), "l"(y)); return d;
}
__device__ __forceinline__ u64 f2fma(u64 x, u64 y, u64 c) {
    u64 d; asm("fma.rn.f32x2 %0,%1,%2,%3;" : "=l"(d) : "l"(x), "l"(y), "l"(c)); return d;
}
__device__ __forceinline__ u64 f2bcast(float v) {
    u64 d; asm("mov.b64 %0,{%1,%1};" : "=l"(d) : "f"(v)); return d;
}
__device__ __forceinline__ float2 f2up(u64 v) {
    float2 f; asm("mov.b64 {%0,%1},%2;" : "=f"(f.x), "=f"(f.y) : "l"(v)); return f;
}
__device__ __forceinline__ u64 f2pack(float lo, float hi) {
    u64 d; asm("mov.b64 %0,{%1,%2};" : "=l"(d) : "f"(lo), "f"(hi)); return d;
}
// cross-lane add of packed f32x2 (full-warp mask; converged call sites)
__device__ __forceinline__ u64 f2shfl_add(u64 v, int o) {
    float2 f = f2up(v);
    f.x += __shfl_xor_sync(0xffffffffu, f.x, o);
    f.y += __shfl_xor_sync(0xffffffffu, f.y, o);
    return f2pack(f.x, f.y);
}
// half2 bits -> packed f32x2 (u64)
__device__ __forceinline__ u64 h2f2(unsigned h) {
    __half2 hh = *reinterpret_cast<__half2*>(&h);
    float2 f = __half22float2(hh);
    return f2pack(f.x, f.y);
}
__device__ __forceinline__ unsigned h2bits(__half2 h) {
    return *reinterpret_cast<unsigned*>(&h);
}

// ---------------- prep body (runs as extra block of count) ----------------
__device__ void prep_body(const float* __restrict__ weight,
                          const float* __restrict__ kgW,
                          const float* __restrict__ att,
                          float* __restrict__ out_cor,
                          float* sW, float* sWk) {
    int t = threadIdx.x;
    int nt = blockDim.x;
    for (int i = t; i < C * C; i += nt) sW[i] = kgW[i];
    __syncthreads();
    for (int i = t; i < N_RELM1 * C; i += nt) {
        int r = i / C, k = i % C;
        float s = 0.f;
        for (int c = 0; c < C; c++) s += weight[r * C + c] * sW[c * C + k];
        sWk[i] = s;
    }
    __syncthreads();
    for (int i = t; i < N_RELM1 * C; i += nt) {
        int r = i / C, c = i % C;
        float s = 0.f;
        for (int k = 0; k < C; k++) s += sW[c * C + k] * sWk[r * C + k];
        g_V[i] = s * INV_SCALE;
    }
    if (t < N_RELM1) {
        float s = 0.f;
        for (int c = 0; c < C; c++) { float w = weight[t * C + c]; s += w * w; }
        g_wn2[t] = s;
    }
    if (t >= 32 && t < 32 + N_FACT) {
        int f = t - 32;
        float a[N_RELM1]; float m = -CUDART_INF_F;
        for (int j = 0; j < N_RELM1; j++) { a[j] = att[f * N_RELM1 + j]; m = fmaxf(m, a[j]); }
        float ssum = 0.f;
        for (int j = 0; j < N_RELM1; j++) { a[j] = expf(a[j] - m); ssum += a[j]; }
        for (int j = 0; j < N_RELM1; j++) a[j] /= ssum;
        for (int c = 0; c < C; c++) {
            float s = 0.f;
            for (int j = 0; j < N_RELM1; j++) s += a[j] * weight[j * C + c];
            g_dw[f * C + c] = s;
        }
    }
    if (t == 64) {
        float rowsum[N_FACT];
        for (int f = 0; f < N_FACT; f++) {
            float s = 0.f;
            for (int j = 0; j < N_RELM1; j++) s += att[f * N_RELM1 + j];
            rowsum[f] = s;
        }
        float cor = 0.f;
        for (int r = 0; r < N_RELM1; r++) {
            float ss = 0.f, ttl = 0.f;
            for (int f = 0; f < N_FACT; f++) {
                float v = att[f * N_RELM1 + r];
                ss += v * v; ttl += v * rowsum[f];
            }
            float n = sqrtf(ss);
            float pos = 0.f;
            for (int f = 0; f < N_FACT; f++) {
                float v = att[f * N_RELM1 + r] / n; pos += v * v;
            }
            cor += (ttl - pos) / TEMPR;
        }
        *out_cor = cor;
    }
    if (t == 65) {
        g_offE[N_ENT] = N_EDGE;
        g_offU[N_USR] = N_EDGE;
    }
}

// ---------------- count (+prep, +fp16 staging) ----------------
__global__ void k_count(const int* __restrict__ head, const int* __restrict__ urows,
                        const float* __restrict__ weight, const float* __restrict__ kgW,
                        const float* __restrict__ att, float* __restrict__ out_cor,
                        const float* __restrict__ ent) {
    __shared__ float sPrep[C * C + N_RELM1 * C];
    if (blockIdx.x == EB) {
        prep_body(weight, kgW, att, out_cor, sPrep, sPrep + C * C);
        return;
    }
    if (blockIdx.x > EB) {   // fp16 staging of entity_emb
        int i4 = (blockIdx.x - EB - 1) * 256 + threadIdx.x;
        float4 v = __ldg(&reinterpret_cast<const float4*>(ent)[i4]);
        uint2 u = make_uint2(h2bits(__floats2half2_rn(v.x, v.y)),
                             h2bits(__floats2half2_rn(v.z, v.w)));
        reinterpret_cast<uint2*>(g_entH)[i4] = u;
        return;
    }
    int e = blockIdx.x * blockDim.x + threadIdx.x;
    if (e >= N_EDGE) return;
    atomicAdd(&g_cntE[head[e]], 1);
    atomicAdd(&g_cntU[urows[e]], 1);
}

// ---------------- scan (decoupled lookback) + score-table blocks ----------------
__global__ void __launch_bounds__(SCAN_B) k_scan(const float* __restrict__ ent) {
    __shared__ __align__(16) float sMem[SCAN_B];
    if (blockIdx.x >= NB_E + NB_U) {
        float (*sVT)[12] = reinterpret_cast<float(*)[12]>(sMem);   // [C][12]
        int t = threadIdx.x;
        for (int i = t; i < N_RELM1 * C; i += SCAN_B) {
            int r = i / C, c = i % C;
            sVT[c][r] = g_V[i];
        }
        __syncthreads();
        int entI = (blockIdx.x - NB_E - NB_U) * SCAN_B + t;
        if (entI >= N_ENT) return;
        float acc[12];
#pragma unroll
        for (int r = 0; r < 12; r++) acc[r] = 0.f;
        const float4* row = &reinterpret_cast<const float4*>(ent)[(size_t)entI * 16];
#pragma unroll 4
        for (int k4 = 0; k4 < 16; k4++) {
            float4 v = __ldg(&row[k4]);
            int c = k4 * 4;
            const float4* vt0 = reinterpret_cast<const float4*>(&sVT[c][0]);
            const float4* vt1 = reinterpret_cast<const float4*>(&sVT[c + 1][0]);
            const float4* vt2 = reinterpret_cast<const float4*>(&sVT[c + 2][0]);
            const float4* vt3 = reinterpret_cast<const float4*>(&sVT[c + 3][0]);
#pragma unroll
            for (int j = 0; j < 3; j++) {
                float4 a0 = vt0[j], a1 = vt1[j], a2 = vt2[j], a3 = vt3[j];
                acc[j*4+0] += v.x*a0.x + v.y*a1.x + v.z*a2.x + v.w*a3.x;
                acc[j*4+1] += v.x*a0.y + v.y*a1.y + v.z*a2.y + v.w*a3.y;
                acc[j*4+2] += v.x*a0.z + v.y*a1.z + v.z*a2.z + v.w*a3.z;
                acc[j*4+3] += v.x*a0.w + v.y*a1.w + v.z*a2.w + v.w*a3.w;
            }
        }
#pragma unroll
        for (int r = 0; r < N_RELM1; r++)
            g_Sme[(size_t)entI * 12 + r] = __expf(acc[r]);
        return;
    }
    int* sh = reinterpret_cast<int*>(sMem);
    __shared__ int sbp;
    bool isE = blockIdx.x < NB_E;
    int b = isE ? blockIdx.x : blockIdx.x - NB_E;
    int n = isE ? N_ENT : N_USR;
    int* cnt  = isE ? g_cntE : g_cntU;
    int* off  = isE ? g_offE : g_offU;
    int* cur  = isE ? g_curE : g_curU;
    int* bsum = isE ? g_bsumE : g_bsumU;
    int* brdy = isE ? g_brdyE : g_brdyU;
    int t = threadIdx.x;
    int i = b * SCAN_B + t;
    int v = (i < n) ? cnt[i] : 0;
    if (i < n) cnt[i] = 0;              // self-zero for next call
    sh[t] = v;
    __syncthreads();
    for (int d = 1; d < SCAN_B; d <<= 1) {
        int u = (t >= d) ? sh[t - d] : 0;
        __syncthreads();
        sh[t] += u;
        __syncthreads();
    }
    int incl = sh[t];
    if (t == SCAN_B - 1) {
        bsum[b] = incl;
        __threadfence();
        atomicExch(&brdy[b], 1);
    }
    if (t < 32) {
        int s = 0;
        for (int j = t; j < b; j += 32) {
            while (atomicAdd(&brdy[j], 0) == 0) { }
            s += atomicAdd(&bsum[j], 0);
        }
#pragma unroll
        for (int o = 16; o; o >>= 1) s += __shfl_xor_sync(0xffffffffu, s, o);
        if (t == 0) sbp = s;
    }
    __syncthreads();
    if (i < n) {
        int o = sbp + incl - v;
        off[i] = o;
        cur[i] = o;
    }
}

// ---------------- fill: CSR payloads + histogram ----------------
__global__ void k_fill(const int* __restrict__ head, const int* __restrict__ tail,
                       const int* __restrict__ etype, const int* __restrict__ urows,
                       const int* __restrict__ ucols, const float* __restrict__ uvals) {
    if (blockIdx.x == 0 && threadIdx.x < 128) {
        g_brdyE[threadIdx.x] = 0;
        g_brdyU[threadIdx.x] = 0;
    }
    int e = blockIdx.x * blockDim.x + threadIdx.x;
    if (e >= N_EDGE) return;
    int h = head[e];
    int ty = etype[e] - 1;
    int p = atomicAdd(&g_curE[h], 1);
    g_pkE[p] = tail[e] | (ty << 20);
    atomicAdd(&g_histE[h], 1ULL << (7 * ty));    // deg<=127 per type: safe
    int q = atomicAdd(&g_curU[urows[e]], 1);
    g_uiP[q] = make_int2(ucols[e], __float_as_int(uvals[e]));
}

// ---------------- kg0 device body (warp = entity; quarter-warp = edge) ----------------
__device__ __forceinline__ void kg0_body(int w, int lane,
                                         const float* __restrict__ ent,
                                         float* __restrict__ out_ent,
                                         const ulonglong2* sW,
                                         const float* sWn, float* sQ) {
    int qtr = lane >> 3, l8 = lane & 7;
    unsigned qm = 0xFFu << (qtr * 8);
    int off = g_offE[w], deg = g_offE[w + 1] - off;

    const ulonglong2* hrow = &reinterpret_cast<const ulonglong2*>(ent)[(size_t)w * 16 + l8 * 2];
    ulonglong2 hv0 = __ldg(hrow);
    ulonglong2 hv1 = __ldg(hrow + 1);

    // softmax1 table q[r] -> shared (per warp)
    float me = (lane < N_RELM1) ? __ldg(&g_Sme[(size_t)w * 12 + lane]) : 0.f;
    u64 hist = g_histE[w];
    if (lane == 0) g_histE[w] = 0ULL;     // self-zero for next call
    int sh7 = 7 * ((lane < N_RELM1) ? lane : 0);
    float part = (lane < N_RELM1) ? (float)(int)((hist >> sh7) & 127ULL) * me : 0.f;
#pragma unroll
    for (int o = 16; o; o >>= 1) part += __shfl_xor_sync(0xffffffffu, part, o);
    float inv1 = 1.f / (part + 1e-16f);
    if (lane < N_RELM1) {
        float qv = me * inv1;
        sQ[lane] = qv * qv * sWn[lane];
    }
    __syncwarp();

    u64 a0 = 0, a1 = 0, a2 = 0, a3 = 0;
    for (int i = qtr; i < deg; i += 4) {
        int pk = __ldg(&g_pkE[off + i]);
        int ty = pk >> 20;
        int tl = pk & 0xFFFFF;
        uint4 raw = __ldg(&reinterpret_cast<const uint4*>(g_entH)[(size_t)tl * 8 + l8]);
        u64 t0 = h2f2(raw.x), t1 = h2f2(raw.y), t2 = h2f2(raw.z), t3 = h2f2(raw.w);
        u64 d = f2mul(t0, hv0.x);
        d = f2fma(t1, hv0.y, d);
        d = f2fma(t2, hv1.x, d);
        d = f2fma(t3, hv1.y, d);
        float2 df = f2up(d);
        float ht = df.x + df.y;
        ht += __shfl_xor_sync(qm, ht, 1, 8);
        ht += __shfl_xor_sync(qm, ht, 2, 8);
        ht += __shfl_xor_sync(qm, ht, 4, 8);
        float e2 = __expf(ht + sQ[ty]);
        ulonglong2 w0 = sW[ty * 16 + l8 * 2];
        ulonglong2 w1 = sW[ty * 16 + l8 * 2 + 1];
        u64 ep = f2bcast(e2);
        a0 = f2fma(f2mul(t0, w0.x), ep, a0);
        a1 = f2fma(f2mul(t1, w0.y), ep, a1);
        a2 = f2fma(f2mul(t2, w1.x), ep, a2);
        a3 = f2fma(f2mul(t3, w1.y), ep, a3);
        if (l8 == 0) g_mask[off + i] = e2;
    }
    __syncwarp();
    // cross-quarter reduce
    a0 = f2shfl_add(a0, 8);  a0 = f2shfl_add(a0, 16);
    a1 = f2shfl_add(a1, 8);  a1 = f2shfl_add(a1, 16);
    a2 = f2shfl_add(a2, 8);  a2 = f2shfl_add(a2, 16);
    a3 = f2shfl_add(a3, 8);  a3 = f2shfl_add(a3, 16);

    u64 s = f2mul(a0, a0);
    s = f2fma(a1, a1, s);
    s = f2fma(a2, a2, s);
    s = f2fma(a3, a3, s);
    float2 sf = f2up(s);
    float ss = sf.x + sf.y;
    ss += __shfl_xor_sync(0xffffffffu, ss, 1);
    ss += __shfl_xor_sync(0xffffffffu, ss, 2);
    ss += __shfl_xor_sync(0xffffffffu, ss, 4);
    float inv = 1.f / fmaxf(sqrtf(ss), 1e-12f);

    if (qtr == 0) {
        u64 ip = f2bcast(inv);
        u64 x0 = f2mul(a0, ip), x1 = f2mul(a1, ip), x2 = f2mul(a2, ip), x3 = f2mul(a3, ip);
        float2 f0 = f2up(x0), f1 = f2up(x1), f2v = f2up(x2), f3 = f2up(x3);
        uint4 uh;
        uh.x = h2bits(__floats2half2_rn(f0.x, f0.y));
        uh.y = h2bits(__floats2half2_rn(f1.x, f1.y));
        uh.z = h2bits(__floats2half2_rn(f2v.x, f2v.y));
        uh.w = h2bits(__floats2half2_rn(f3.x, f3.y));
        reinterpret_cast<uint4*>(g_entAH)[(size_t)w * 8 + l8] = uh;
        ulonglong2 o0, o1;
        o0.x = f2add(hv0.x, x0); o0.y = f2add(hv0.y, x1);
        o1.x = f2add(hv1.x, x2); o1.y = f2add(hv1.y, x3);
        ulonglong2* orow = &reinterpret_cast<ulonglong2*>(out_ent)[(size_t)w * 16 + l8 * 2];
        orow[0] = o0;
        orow[1] = o1;
    }
}

// ---------------- kg1 device body ----------------
__device__ __forceinline__ void kg1_body(int w, int lane,
                                         float* __restrict__ out_ent,
                                         const ulonglong2* sW) {
    int qtr = lane >> 3, l8 = lane & 7;
    int off = g_offE[w], deg = g_offE[w + 1] - off;

    u64 a0 = 0, a1 = 0, a2 = 0, a3 = 0;
    for (int i = qtr; i < deg; i += 4) {
        int pk = __ldg(&g_pkE[off + i]);
        float m = __ldg(&g_mask[off + i]);
        int ty = pk >> 20;
        int tl = pk & 0xFFFFF;
        uint4 raw = __ldg(&reinterpret_cast<const uint4*>(g_entAH)[(size_t)tl * 8 + l8]);
        ulonglong2 w0 = sW[ty * 16 + l8 * 2];
        ulonglong2 w1 = sW[ty * 16 + l8 * 2 + 1];
        u64 mp = f2bcast(m);
        a0 = f2fma(f2mul(h2f2(raw.x), w0.x), mp, a0);
        a1 = f2fma(f2mul(h2f2(raw.y), w0.y), mp, a1);
        a2 = f2fma(f2mul(h2f2(raw.z), w1.x), mp, a2);
        a3 = f2fma(f2mul(h2f2(raw.w), w1.y), mp, a3);
    }
    __syncwarp();
    a0 = f2shfl_add(a0, 8);  a0 = f2shfl_add(a0, 16);
    a1 = f2shfl_add(a1, 8);  a1 = f2shfl_add(a1, 16);
    a2 = f2shfl_add(a2, 8);  a2 = f2shfl_add(a2, 16);
    a3 = f2shfl_add(a3, 8);  a3 = f2shfl_add(a3, 16);

    u64 s = f2mul(a0, a0);
    s = f2fma(a1, a1, s);
    s = f2fma(a2, a2, s);
    s = f2fma(a3, a3, s);
    float2 sf = f2up(s);
    float ss = sf.x + sf.y;
    ss += __shfl_xor_sync(0xffffffffu, ss, 1);
    ss += __shfl_xor_sync(0xffffffffu, ss, 2);
    ss += __shfl_xor_sync(0xffffffffu, ss, 4);
    float inv = 1.f / fmaxf(sqrtf(ss), 1e-12f);

    if (qtr == 0) {
        u64 ip = f2bcast(inv);
        ulonglong2* orow = &reinterpret_cast<ulonglong2*>(out_ent)[(size_t)w * 16 + l8 * 2];
        ulonglong2 o0 = orow[0], o1 = orow[1];
        o0.x = f2fma(a0, ip, o0.x); o0.y = f2fma(a1, ip, o0.y);
        o1.x = f2fma(a2, ip, o1.x); o1.y = f2fma(a3, ip, o1.y);
        orow[0] = o0;
        orow[1] = o1;
    }
}

// ---------------- ui device body ----------------
template <int HOP>
__device__ __forceinline__ void ui_body(int u, int lane,
                                        const float* __restrict__ user_emb,
                                        float* __restrict__ out_usr,
                                        const ulonglong2* sL, const ulonglong2* sD) {
    int qtr = lane >> 3, l8 = lane & 7;
    unsigned qm = 0xFFu << (qtr * 8);
    const float*  usr_src = (HOP == 0) ? user_emb : g_usrA;
    const __half* entH    = (HOP == 0) ? g_entH : g_entAH;

    const ulonglong2* urow = &reinterpret_cast<const ulonglong2*>(usr_src)[(size_t)u * 16 + l8 * 2];
    ulonglong2 uv0 = __ldg(urow);
    ulonglong2 uv1 = __ldg(urow + 1);

    // quarter qtr computes dot(u, latent[qtr])
    ulonglong2 L0 = sL[qtr * 16 + l8 * 2];
    ulonglong2 L1 = sL[qtr * 16 + l8 * 2 + 1];
    u64 dd = f2mul(uv0.x, L0.x);
    dd = f2fma(uv0.y, L0.y, dd);
    dd = f2fma(uv1.x, L1.x, dd);
    dd = f2fma(uv1.y, L1.y, dd);
    float2 ddf = f2up(dd);
    float dq = ddf.x + ddf.y;
    dq += __shfl_xor_sync(qm, dq, 1, 8);
    dq += __shfl_xor_sync(qm, dq, 2, 8);
    dq += __shfl_xor_sync(qm, dq, 4, 8);
    __syncwarp();
    float d0 = __shfl_sync(0xffffffffu, dq, 0);
    float d1 = __shfl_sync(0xffffffffu, dq, 8);
    float d2 = __shfl_sync(0xffffffffu, dq, 16);
    float d3 = __shfl_sync(0xffffffffu, dq, 24);
    float m = fmaxf(fmaxf(d0, d1), fmaxf(d2, d3));
    d0 = __expf(d0 - m); d1 = __expf(d1 - m); d2 = __expf(d2 - m); d3 = __expf(d3 - m);
    float invs = 1.f / (d0 + d1 + d2 + d3);
    d0 *= invs; d1 *= invs; d2 *= invs; d3 *= invs;

    int off = g_offU[u], deg = g_offU[u + 1] - off;
    u64 a0 = 0, a1 = 0, a2 = 0, a3 = 0;
    for (int i = qtr; i < deg; i += 4) {
        int2 p = __ldg(&g_uiP[off + i]);
        u64 vp = f2bcast(__int_as_float(p.y));
        uint4 raw = __ldg(&reinterpret_cast<const uint4*>(entH)[(size_t)p.x * 8 + l8]);
        a0 = f2fma(h2f2(raw.x), vp, a0);
        a1 = f2fma(h2f2(raw.y), vp, a1);
        a2 = f2fma(h2f2(raw.z), vp, a2);
        a3 = f2fma(h2f2(raw.w), vp, a3);
    }
    __syncwarp();
    a0 = f2shfl_add(a0, 8);  a0 = f2shfl_add(a0, 16);
    a1 = f2shfl_add(a1, 8);  a1 = f2shfl_add(a1, 16);
    a2 = f2shfl_add(a2, 8);  a2 = f2shfl_add(a2, 16);
    a3 = f2shfl_add(a3, 8);  a3 = f2shfl_add(a3, 16);

    // mix = 1 + sum_f d_f * dw_f  (per lane's 8 columns)
    u64 one = f2bcast(1.f);
    u64 p0 = f2bcast(d0), p1 = f2bcast(d1), p2 = f2bcast(d2), p3 = f2bcast(d3);
    ulonglong2 b00 = sD[0 * 16 + l8 * 2], b01 = sD[0 * 16 + l8 * 2 + 1];
    ulonglong2 b10 = sD[1 * 16 + l8 * 2], b11 = sD[1 * 16 + l8 * 2 + 1];
    ulonglong2 b20 = sD[2 * 16 + l8 * 2], b21 = sD[2 * 16 + l8 * 2 + 1];
    ulonglong2 b30 = sD[3 * 16 + l8 * 2], b31 = sD[3 * 16 + l8 * 2 + 1];
    u64 m0 = f2fma(b00.x, p0, one); m0 = f2fma(b10.x, p1, m0); m0 = f2fma(b20.x, p2, m0); m0 = f2fma(b30.x, p3, m0);
    u64 m1 = f2fma(b00.y, p0, one); m1 = f2fma(b10.y, p1, m1); m1 = f2fma(b20.y, p2, m1); m1 = f2fma(b30.y, p3, m1);
    u64 m2 = f2fma(b01.x, p0, one); m2 = f2fma(b11.x, p1, m2); m2 = f2fma(b21.x, p2, m2); m2 = f2fma(b31.x, p3, m2);
    u64 m3 = f2fma(b01.y, p0, one); m3 = f2fma(b11.y, p1, m3); m3 = f2fma(b21.y, p2, m3); m3 = f2fma(b31.y, p3, m3);

    u64 x0 = f2mul(a0, m0), x1 = f2mul(a1, m1), x2 = f2mul(a2, m2), x3 = f2mul(a3, m3);
    u64 s = f2mul(x0, x0);
    s = f2fma(x1, x1, s);
    s = f2fma(x2, x2, s);
    s = f2fma(x3, x3, s);
    float2 sf = f2up(s);
    float ss = sf.x + sf.y;
    ss += __shfl_xor_sync(0xffffffffu, ss, 1);
    ss += __shfl_xor_sync(0xffffffffu, ss, 2);
    ss += __shfl_xor_sync(0xffffffffu, ss, 4);
    float inv = 1.f / fmaxf(sqrtf(ss), 1e-12f);

    if (qtr == 0) {
        u64 ip = f2bcast(inv);
        x0 = f2mul(x0, ip); x1 = f2mul(x1, ip); x2 = f2mul(x2, ip); x3 = f2mul(x3, ip);
        ulonglong2* orow = &reinterpret_cast<ulonglong2*>(out_usr)[(size_t)u * 16 + l8 * 2];
        if (HOP == 0) {
            ulonglong2 w0, w1;
            w0.x = x0; w0.y = x1; w1.x = x2; w1.y = x3;
            ulonglong2* arow = &reinterpret_cast<ulonglong2*>(g_usrA)[(size_t)u * 16 + l8 * 2];
            arow[0] = w0;
            arow[1] = w1;
            ulonglong2 o0, o1;
            o0.x = f2add(uv0.x, x0); o0.y = f2add(uv0.y, x1);
            o1.x = f2add(uv1.x, x2); o1.y = f2add(uv1.y, x3);
            orow[0] = o0;
            orow[1] = o1;
        } else {
            ulonglong2 o0 = orow[0], o1 = orow[1];
            o0.x = f2add(o0.x, x0); o0.y = f2add(o0.y, x1);
            o1.x = f2add(o1.x, x2); o1.y = f2add(o1.y, x3);
            orow[0] = o0;
            orow[1] = o1;
        }
    }
}

// ---------------- fused hop kernels ----------------
__global__ void __launch_bounds__(256) k_fused0(const float* __restrict__ ent,
                                                const float* __restrict__ usr,
                                                const float* __restrict__ latent,
                                                const float* __restrict__ weight,
                                                float* __restrict__ out_ent,
                                                float* __restrict__ out_usr) {
    __shared__ __align__(16) float4 sW[N_RELM1 * 16];
    __shared__ __align__(16) float4 sA[N_FACT * 16];
    __shared__ __align__(16) float4 sB[N_FACT * 16];
    __shared__ float sWn[N_RELM1];
    __shared__ float sQ[8][12];
    int t = threadIdx.x;
    bool isKG = blockIdx.x < KGB;
    if (isKG) {
        for (int i = t; i < N_RELM1 * 16; i += 256)
            sW[i] = reinterpret_cast<const float4*>(weight)[i];
        if (t < N_RELM1) sWn[t] = g_wn2[t];
    } else {
        if (t < N_FACT * 16) {
            sA[t] = reinterpret_cast<const float4*>(latent)[t];
            sB[t] = reinterpret_cast<const float4*>(g_dw)[t];
        }
    }
    __syncthreads();
    int lane = t & 31, wid = t >> 5;
    if (isKG)
        kg0_body(blockIdx.x * 8 + wid, lane, ent, out_ent,
                 reinterpret_cast<const ulonglong2*>(sW), sWn, sQ[wid]);
    else
        ui_body<0>((blockIdx.x - KGB) * 8 + wid, lane, usr, out_usr,
                   reinterpret_cast<const ulonglong2*>(sA),
                   reinterpret_cast<const ulonglong2*>(sB));
}

__global__ void __launch_bounds__(256) k_fused1(const float* __restrict__ usr,
                                                const float* __restrict__ latent,
                                                const float* __restrict__ weight,
                                                float* __restrict__ out_ent,
                                                float* __restrict__ out_usr) {
    __shared__ __align__(16) float4 sW[N_RELM1 * 16];
    __shared__ __align__(16) float4 sA[N_FACT * 16];
    __shared__ __align__(16) float4 sB[N_FACT * 16];
    int t = threadIdx.x;
    bool isKG = blockIdx.x < KGB;
    if (isKG) {
        for (int i = t; i < N_RELM1 * 16; i += 256)
            sW[i] = reinterpret_cast<const float4*>(weight)[i];
    } else {
        if (t < N_FACT * 16) {
            sA[t] = reinterpret_cast<const float4*>(latent)[t];
            sB[t] = reinterpret_cast<const float4*>(g_dw)[t];
        }
    }
    __syncthreads();
    int lane = t & 31, wid = t >> 5;
    if (isKG)
        kg1_body(blockIdx.x * 8 + wid, lane, out_ent,
                 reinterpret_cast<const ulonglong2*>(sW));
    else
        ui_body<1>((blockIdx.x - KGB) * 8 + wid, lane, usr, out_usr,
                   reinterpret_cast<const ulonglong2*>(sA),
                   reinterpret_cast<const ulonglong2*>(sB));
}

// ---------------- launch ----------------
extern "C" void kernel_launch(void* const* d_in, const int* in_sizes, int n_in,
                              void* d_out, int out_size) {
    const float* user_emb   = (const float*)d_in[0];
    const float* entity_emb = (const float*)d_in[1];
    const float* latent     = (const float*)d_in[2];
    const float* weight     = (const float*)d_in[3];
    const float* att        = (const float*)d_in[4];
    const float* kgW        = (const float*)d_in[5];
    const float* ui_vals    = (const float*)d_in[6];
    const int*   edge_index = (const int*)d_in[7];
    const int*   etype      = (const int*)d_in[8];
    const int*   ui_rows    = (const int*)d_in[9];
    const int*   ui_cols    = (const int*)d_in[10];

    const int* head = edge_index;
    const int* tail = edge_index + N_EDGE;

    float* out     = (float*)d_out;
    float* out_ent = out;
    float* out_usr = out + (size_t)N_ENT * C;
    float* out_cor = out + (size_t)N_ENT * C + (size_t)N_USR * C;

    const int TB = 256;

    k_count<<<EB + 1 + HB, TB>>>(head, ui_rows, weight, kgW, att, out_cor,
                                 entity_emb);                            // 1 (+prep+stage)
    k_scan<<<NB_E + NB_U + SBK, SCAN_B>>>(entity_emb);                   // 2 (+score table)
    k_fill<<<EB, TB>>>(head, tail, etype, ui_rows, ui_cols, ui_vals);    // 3 (+hist)
    k_fused0<<<KGB + UIB, TB>>>(entity_emb, user_emb, latent, weight,    // 4 (profiled)
                                out_ent, out_usr);
    k_fused1<<<KGB + UIB, TB>>>(user_emb, latent, weight,                // 5
                                out_ent, out_usr);
}